// round 9
// baseline (speedup 1.0000x reference)
#include <cuda_runtime.h>

#define BB 32
#define NN 128
#define HH 100
#define ROWS (BB*NN)    // 4096

// Scratch (static device allocations — allowed)
__device__ float g_hidden[ROWS*HH];
__device__ float g_hv[ROWS*HH];
__device__ float g_hw[ROWS*HH];
__device__ float g_msg[ROWS*HH];
__device__ float g_gterm[ROWS*HH];
__device__ int   g_nodemask[ROWS];

typedef unsigned long long u64;

__device__ __forceinline__ u64 fma2(u64 a, u64 b, u64 c) {
    u64 d;
    asm("fma.rn.f32x2 %0, %1, %2, %3;" : "=l"(d) : "l"(a), "l"(b), "l"(c));
    return d;
}
__device__ __forceinline__ u64 add2(u64 a, u64 b) {
    u64 d;
    asm("add.rn.f32x2 %0, %1, %2;" : "=l"(d) : "l"(a), "l"(b));
    return d;
}
__device__ __forceinline__ u64 pack2(float w) {
    u64 d;
    asm("mov.b64 %0, {%1, %1};" : "=l"(d) : "f"(w));
    return d;
}
__device__ __forceinline__ u64 packlh(float lo, float hi) {
    u64 d;
    asm("mov.b64 %0, {%1, %2};" : "=l"(d) : "f"(lo), "f"(hi));
    return d;
}
__device__ __forceinline__ void unpack2(u64 v, float& lo, float& hi) {
    asm("mov.b64 {%0, %1}, %2;" : "=f"(lo), "=f"(hi) : "l"(v));
}
__device__ __forceinline__ u64 relu2(u64 v) {
    float lo, hi;
    unpack2(v, lo, hi);
    return packlh(fmaxf(lo, 0.f), fmaxf(hi, 0.f));
}

// ---------------------------------------------------------------------------
// init + mask + proj of pass 1. Block = 4 rows, 128 threads, grid 1024.
// ---------------------------------------------------------------------------
__global__ void __launch_bounds__(128)
k_init_proj(const float* __restrict__ nodes, const float* __restrict__ edges,
            const float* __restrict__ Wv, const float* __restrict__ Ww) {
    __shared__ float4 sP[HH];        // nodes transposed: sP[k] = rows 0..3
    int base = blockIdx.x * 4;
    int tid  = threadIdx.x;

    {
        int r = tid >> 5, lane = tid & 31;
        const float4* e4 = (const float4*)edges + (size_t)(base + r) * NN;
        float s = 0.f;
        #pragma unroll
        for (int j = 0; j < 4; j++) {
            float4 e = e4[lane + 32*j];
            s += (e.x + e.y) + (e.z + e.w);
        }
        #pragma unroll
        for (int off = 16; off > 0; off >>= 1)
            s += __shfl_xor_sync(0xffffffffu, s, off);
        if (lane == 0) g_nodemask[base + r] = (s != 0.0f) ? 1 : 0;
    }

    if (tid < HH) {
        int h = tid;
        float x0 = nodes[(size_t)(base+0)*HH + h];
        float x1 = nodes[(size_t)(base+1)*HH + h];
        float x2 = nodes[(size_t)(base+2)*HH + h];
        float x3 = nodes[(size_t)(base+3)*HH + h];
        g_hidden[(size_t)(base+0)*HH + h] = x0;
        g_hidden[(size_t)(base+1)*HH + h] = x1;
        g_hidden[(size_t)(base+2)*HH + h] = x2;
        g_hidden[(size_t)(base+3)*HH + h] = x3;
        sP[h] = make_float4(x0, x1, x2, x3);
    }
    __syncthreads();

    if (tid < HH) {
        int h = tid;
        const ulonglong2* sP2 = (const ulonglong2*)sP;
        u64 v01=0, v23=0, w01=0, w23=0;
        #pragma unroll 4
        for (int k = 0; k < HH; k++) {
            ulonglong2 x = sP2[k];
            u64 wv = pack2(Wv[k*HH + h]);
            u64 ww = pack2(Ww[k*HH + h]);
            v01 = fma2(x.x, wv, v01); v23 = fma2(x.y, wv, v23);
            w01 = fma2(x.x, ww, w01); w23 = fma2(x.y, ww, w23);
        }
        float a,b,c,d, e,f,g,q;
        unpack2(v01, a, b); unpack2(v23, c, d);
        unpack2(w01, e, f); unpack2(w23, g, q);
        g_hv[(size_t)(base+0)*HH + h] = a;
        g_hv[(size_t)(base+1)*HH + h] = b;
        g_hv[(size_t)(base+2)*HH + h] = c;
        g_hv[(size_t)(base+3)*HH + h] = d;
        g_hw[(size_t)(base+0)*HH + h] = e;
        g_hw[(size_t)(base+1)*HH + h] = f;
        g_hw[(size_t)(base+2)*HH + h] = g;
        g_hw[(size_t)(base+3)*HH + h] = q;
    }
}

// ---------------------------------------------------------------------------
// msg: messages[b,v,h] = sum_w [adj!=0] * relu(hv[v,h] + hw[w,h] + e.We)
// Block = 4 v-rows, 256 threads = (vloc = tid&3, q = tid>>2), h-pair = 2q,
// q < 50 (warps 6-7 exit after staging). ALL inner-loop operands in smem:
//   s_hw2 : hw as genuine {h,h+1} u64 pairs for the whole batch  (51200 B)
//   s_e2  : pre-dup'd {e,e} packs for the 4 v-rows               (16384 B)
//   s_m2  : pre-dup'd {m,m} masks                                 (4096 B)
// total 71680 B dynamic -> 3 blocks/SM, 24 warps/SM. grid = 1024.
// Inner per w per h-pair: 2 LDS.128 + 2 LDS.64 + add2 + 5 fma2 + 3 relu ops.
// ---------------------------------------------------------------------------
__global__ void __launch_bounds__(256)
k_msg(const float* __restrict__ edges, const float* __restrict__ We) {
    extern __shared__ u64 sm[];
    u64* s_hw2 = sm;                   // [w*50 + p]
    u64* s_e2  = sm + 6400;            // [(v*128 + w)*4 + j]
    u64* s_m2  = sm + 6400 + 2048;     // [v*128 + w]

    int bx  = blockIdx.x;
    int b   = bx >> 5;
    int v0  = (bx & 31) * 4;
    int tid = threadIdx.x;
    int bN  = b * NN;

    // stage hw pairs for the whole batch (128 rows x 50 pairs)
    for (int i = tid; i < 6400; i += 256) {
        int w = i / 50, p = i - w*50;
        s_hw2[i] = *(const u64*)(g_hw + (size_t)(bN + w)*HH + 2*p);
    }
    // stage edges (dup'd) + masks (dup'd) for 4 v-rows
    for (int i = tid; i < 512; i += 256) {
        int v = i >> 7, w = i & 127;
        float4 e = ((const float4*)edges)[(size_t)(bN + v0 + v)*NN + w];
        u64* dst = s_e2 + i*4;
        dst[0] = pack2(e.x); dst[1] = pack2(e.y);
        dst[2] = pack2(e.z); dst[3] = pack2(e.w);
        float s = (e.x + e.y) + (e.z + e.w);
        s_m2[i] = pack2((s != 0.0f) ? 1.0f : 0.0f);
    }
    __syncthreads();

    int vloc = tid & 3;
    int q    = tid >> 2;
    if (q < 50) {
        int h0  = 2*q;
        int row = bN + v0 + vloc;
        u64 hv2 = *(const u64*)(g_hv + (size_t)row*HH + h0);
        u64 we0 = *(const u64*)(We + 0*HH + h0);
        u64 we1 = *(const u64*)(We + 1*HH + h0);
        u64 we2 = *(const u64*)(We + 2*HH + h0);
        u64 we3 = *(const u64*)(We + 3*HH + h0);

        const u64* ev  = s_e2 + vloc*512;
        const u64* mv  = s_m2 + vloc*128;
        const u64* hwp = s_hw2 + q;

        u64 acc0 = 0, acc1 = 0;
        #pragma unroll 4
        for (int w = 0; w < NN; w += 2) {
            // w
            ulonglong2 eA0 = *(const ulonglong2*)(ev + w*4);
            ulonglong2 eB0 = *(const ulonglong2*)(ev + w*4 + 2);
            u64 p0 = add2(hv2, hwp[w*50]);
            p0 = fma2(eA0.x, we0, p0);
            p0 = fma2(eA0.y, we1, p0);
            p0 = fma2(eB0.x, we2, p0);
            p0 = fma2(eB0.y, we3, p0);
            acc0 = fma2(relu2(p0), mv[w], acc0);
            // w+1 (independent chain)
            ulonglong2 eA1 = *(const ulonglong2*)(ev + (w+1)*4);
            ulonglong2 eB1 = *(const ulonglong2*)(ev + (w+1)*4 + 2);
            u64 p1 = add2(hv2, hwp[(w+1)*50]);
            p1 = fma2(eA1.x, we0, p1);
            p1 = fma2(eA1.y, we1, p1);
            p1 = fma2(eB1.x, we2, p1);
            p1 = fma2(eB1.y, we3, p1);
            acc1 = fma2(relu2(p1), mv[w+1], acc1);
        }
        u64 acc = add2(acc0, acc1);
        float a0, a1; unpack2(acc, a0, a1);
        *(float2*)(g_msg + (size_t)row*HH + h0) = make_float2(a0, a1);
    }
}

// ---------------------------------------------------------------------------
// update (masked tanh) fused with proj of the NEW hidden. 4 rows, 128 thr,
// grid 1024.
// ---------------------------------------------------------------------------
__global__ void __launch_bounds__(128)
k_updproj(const float* __restrict__ Wu, const float* __restrict__ Wv,
          const float* __restrict__ Ww) {
    __shared__ float4 sU[2*HH];      // [hidden; msg] transposed
    __shared__ float4 sP[HH];        // new hidden transposed
    int base = blockIdx.x * 4;
    int tid  = threadIdx.x;
    float* sUf = (float*)sU;

    for (int i = tid; i < 4*2*HH; i += 128) {
        int r = i / (2*HH), k = i - r*(2*HH);
        float x = (k < HH) ? g_hidden[(size_t)(base + r)*HH + k]
                           : g_msg   [(size_t)(base + r)*HH + (k - HH)];
        sUf[k*4 + r] = x;
    }
    __syncthreads();

    if (tid < HH) {
        int h = tid;
        const ulonglong2* sU2 = (const ulonglong2*)sU;
        u64 a01=0, a23=0;
        #pragma unroll 4
        for (int k = 0; k < 2*HH; k++) {
            ulonglong2 x = sU2[k];
            u64 w = pack2(Wu[k*HH + h]);
            a01 = fma2(x.x, w, a01);
            a23 = fma2(x.y, w, a23);
        }
        float f0,f1,f2,f3;
        unpack2(a01, f0, f1); unpack2(a23, f2, f3);
        float n0 = g_nodemask[base+0] ? tanhf(f0) : sUf[h*4+0];
        float n1 = g_nodemask[base+1] ? tanhf(f1) : sUf[h*4+1];
        float n2 = g_nodemask[base+2] ? tanhf(f2) : sUf[h*4+2];
        float n3 = g_nodemask[base+3] ? tanhf(f3) : sUf[h*4+3];
        g_hidden[(size_t)(base+0)*HH + h] = n0;
        g_hidden[(size_t)(base+1)*HH + h] = n1;
        g_hidden[(size_t)(base+2)*HH + h] = n2;
        g_hidden[(size_t)(base+3)*HH + h] = n3;
        sP[h] = make_float4(n0, n1, n2, n3);
    }
    __syncthreads();

    if (tid < HH) {
        int h = tid;
        const ulonglong2* sP2 = (const ulonglong2*)sP;
        u64 v01=0, v23=0, w01=0, w23=0;
        #pragma unroll 4
        for (int k = 0; k < HH; k++) {
            ulonglong2 x = sP2[k];
            u64 wv = pack2(Wv[k*HH + h]);
            u64 ww = pack2(Ww[k*HH + h]);
            v01 = fma2(x.x, wv, v01); v23 = fma2(x.y, wv, v23);
            w01 = fma2(x.x, ww, w01); w23 = fma2(x.y, ww, w23);
        }
        float a,b,c,d, e,f,g,q;
        unpack2(v01, a, b); unpack2(v23, c, d);
        unpack2(w01, e, f); unpack2(w23, g, q);
        g_hv[(size_t)(base+0)*HH + h] = a;
        g_hv[(size_t)(base+1)*HH + h] = b;
        g_hv[(size_t)(base+2)*HH + h] = c;
        g_hv[(size_t)(base+3)*HH + h] = d;
        g_hw[(size_t)(base+0)*HH + h] = e;
        g_hw[(size_t)(base+1)*HH + h] = f;
        g_hw[(size_t)(base+2)*HH + h] = g;
        g_hw[(size_t)(base+3)*HH + h] = q;
    }
}

// ---------------------------------------------------------------------------
// final update fused with readout gterm. No g_hidden write needed.
// ---------------------------------------------------------------------------
__global__ void __launch_bounds__(128)
k_updread(const float* __restrict__ nodes, const float* __restrict__ Wu,
          const float* __restrict__ Wr) {
    __shared__ float4 sU[2*HH];      // [hidden; msg]
    __shared__ float4 sR[2*HH];      // [new_hidden; nodes]
    int base = blockIdx.x * 4;
    int tid  = threadIdx.x;
    float* sUf = (float*)sU;
    float* sRf = (float*)sR;

    for (int i = tid; i < 4*2*HH; i += 128) {
        int r = i / (2*HH), k = i - r*(2*HH);
        float x = (k < HH) ? g_hidden[(size_t)(base + r)*HH + k]
                           : g_msg   [(size_t)(base + r)*HH + (k - HH)];
        sUf[k*4 + r] = x;
    }
    for (int i = tid; i < 4*HH; i += 128) {
        int r = i / HH, k = i - r*HH;
        sRf[(HH + k)*4 + r] = nodes[(size_t)(base + r)*HH + k];
    }
    __syncthreads();

    if (tid < HH) {
        int h = tid;
        const ulonglong2* sU2 = (const ulonglong2*)sU;
        u64 a01=0, a23=0;
        #pragma unroll 4
        for (int k = 0; k < 2*HH; k++) {
            ulonglong2 x = sU2[k];
            u64 w = pack2(Wu[k*HH + h]);
            a01 = fma2(x.x, w, a01);
            a23 = fma2(x.y, w, a23);
        }
        float f0,f1,f2,f3;
        unpack2(a01, f0, f1); unpack2(a23, f2, f3);
        float n0 = g_nodemask[base+0] ? tanhf(f0) : sUf[h*4+0];
        float n1 = g_nodemask[base+1] ? tanhf(f1) : sUf[h*4+1];
        float n2 = g_nodemask[base+2] ? tanhf(f2) : sUf[h*4+2];
        float n3 = g_nodemask[base+3] ? tanhf(f3) : sUf[h*4+3];
        sR[h] = make_float4(n0, n1, n2, n3);
    }
    __syncthreads();

    if (tid < HH) {
        int h = tid;
        const ulonglong2* sR2 = (const ulonglong2*)sR;
        u64 a01=0, a23=0;
        #pragma unroll 4
        for (int k = 0; k < 2*HH; k++) {
            ulonglong2 x = sR2[k];
            u64 w = pack2(Wr[k*HH + h]);
            a01 = fma2(x.x, w, a01);
            a23 = fma2(x.y, w, a23);
        }
        float f0,f1,f2,f3;
        unpack2(a01, f0, f1); unpack2(a23, f2, f3);
        float m0 = g_nodemask[base+0] ? 1.f : 0.f;
        float m1 = g_nodemask[base+1] ? 1.f : 0.f;
        float m2 = g_nodemask[base+2] ? 1.f : 0.f;
        float m3 = g_nodemask[base+3] ? 1.f : 0.f;
        g_gterm[(size_t)(base+0)*HH + h] = fmaxf(f0, 0.f) * m0;
        g_gterm[(size_t)(base+1)*HH + h] = fmaxf(f1, 0.f) * m1;
        g_gterm[(size_t)(base+2)*HH + h] = fmaxf(f2, 0.f) * m2;
        g_gterm[(size_t)(base+3)*HH + h] = fmaxf(f3, 0.f) * m3;
    }
}

// ---------------------------------------------------------------------------
// reduce: out[b,h] = sum_v gterm[b,v,h]  (deterministic, no atomics)
// ---------------------------------------------------------------------------
__global__ void k_reduce(float* __restrict__ out) {
    int b   = blockIdx.x;
    int tid = threadIdx.x;           // 512
    int q   = tid >> 7;
    int h   = tid & 127;
    __shared__ float red[4][128];
    float acc = 0.f;
    if (h < HH) {
        int v0 = q * 32;
        #pragma unroll 4
        for (int v = v0; v < v0 + 32; v++)
            acc += g_gterm[(size_t)(b*NN + v)*HH + h];
    }
    red[q][h] = acc;
    __syncthreads();
    if (q == 0 && h < HH)
        out[b*HH + h] = (red[0][h] + red[1][h]) + (red[2][h] + red[3][h]);
}

extern "C" void kernel_launch(void* const* d_in, const int* in_sizes, int n_in,
                              void* d_out, int out_size) {
    const float* nodes = (const float*)d_in[0];
    const float* edges = (const float*)d_in[1];
    const float* Wv    = (const float*)d_in[2];
    const float* Ww    = (const float*)d_in[3];
    const float* We    = (const float*)d_in[4];
    const float* Wu    = (const float*)d_in[5];
    const float* Wr    = (const float*)d_in[6];
    float* out = (float*)d_out;

    cudaFuncSetAttribute(k_msg, cudaFuncAttributeMaxDynamicSharedMemorySize, 71680);

    k_init_proj<<<ROWS/4, 128>>>(nodes, edges, Wv, Ww);
    for (int p = 0; p < 2; p++) {
        k_msg<<<1024, 256, 71680>>>(edges, We);
        k_updproj<<<ROWS/4, 128>>>(Wu, Wv, Ww);
    }
    k_msg<<<1024, 256, 71680>>>(edges, We);
    k_updread<<<ROWS/4, 128>>>(nodes, Wu, Wr);
    k_reduce<<<BB, 512>>>(out);
}

// round 10
// speedup vs baseline: 1.8929x; 1.8929x over previous
#include <cuda_runtime.h>

#define BB 32
#define NN 128
#define HH 100
#define ROWS (BB*NN)    // 4096

// padded per-vloc strides (u64 units) to avoid 4-way bank conflicts:
// 514*8/4 % 32 = 4 and 130*8/4 % 32 = 4  -> each vloc slice shifted 4 banks
#define EV_STRIDE 514
#define MV_STRIDE 130

// Scratch (static device allocations — allowed)
__device__ float g_hidden[ROWS*HH];
__device__ float g_hv[ROWS*HH];
__device__ float g_hw[ROWS*HH];
__device__ float g_msg[ROWS*HH];
__device__ float g_gterm[ROWS*HH];
__device__ int   g_nodemask[ROWS];

typedef unsigned long long u64;

__device__ __forceinline__ u64 fma2(u64 a, u64 b, u64 c) {
    u64 d;
    asm("fma.rn.f32x2 %0, %1, %2, %3;" : "=l"(d) : "l"(a), "l"(b), "l"(c));
    return d;
}
__device__ __forceinline__ u64 add2(u64 a, u64 b) {
    u64 d;
    asm("add.rn.f32x2 %0, %1, %2;" : "=l"(d) : "l"(a), "l"(b));
    return d;
}
__device__ __forceinline__ u64 pack2(float w) {
    u64 d;
    asm("mov.b64 %0, {%1, %1};" : "=l"(d) : "f"(w));
    return d;
}
__device__ __forceinline__ u64 packlh(float lo, float hi) {
    u64 d;
    asm("mov.b64 %0, {%1, %2};" : "=l"(d) : "f"(lo), "f"(hi));
    return d;
}
__device__ __forceinline__ void unpack2(u64 v, float& lo, float& hi) {
    asm("mov.b64 {%0, %1}, %2;" : "=f"(lo), "=f"(hi) : "l"(v));
}
__device__ __forceinline__ u64 relu2(u64 v) {
    float lo, hi;
    unpack2(v, lo, hi);
    return packlh(fmaxf(lo, 0.f), fmaxf(hi, 0.f));
}

// ---------------------------------------------------------------------------
// init + mask + proj of pass 1. Block = 4 rows, 128 threads, grid 1024.
// ---------------------------------------------------------------------------
__global__ void __launch_bounds__(128)
k_init_proj(const float* __restrict__ nodes, const float* __restrict__ edges,
            const float* __restrict__ Wv, const float* __restrict__ Ww) {
    __shared__ float4 sP[HH];        // nodes transposed: sP[k] = rows 0..3
    int base = blockIdx.x * 4;
    int tid  = threadIdx.x;

    {
        int r = tid >> 5, lane = tid & 31;
        const float4* e4 = (const float4*)edges + (size_t)(base + r) * NN;
        float s = 0.f;
        #pragma unroll
        for (int j = 0; j < 4; j++) {
            float4 e = e4[lane + 32*j];
            s += (e.x + e.y) + (e.z + e.w);
        }
        #pragma unroll
        for (int off = 16; off > 0; off >>= 1)
            s += __shfl_xor_sync(0xffffffffu, s, off);
        if (lane == 0) g_nodemask[base + r] = (s != 0.0f) ? 1 : 0;
    }

    if (tid < HH) {
        int h = tid;
        float x0 = nodes[(size_t)(base+0)*HH + h];
        float x1 = nodes[(size_t)(base+1)*HH + h];
        float x2 = nodes[(size_t)(base+2)*HH + h];
        float x3 = nodes[(size_t)(base+3)*HH + h];
        g_hidden[(size_t)(base+0)*HH + h] = x0;
        g_hidden[(size_t)(base+1)*HH + h] = x1;
        g_hidden[(size_t)(base+2)*HH + h] = x2;
        g_hidden[(size_t)(base+3)*HH + h] = x3;
        sP[h] = make_float4(x0, x1, x2, x3);
    }
    __syncthreads();

    if (tid < HH) {
        int h = tid;
        const ulonglong2* sP2 = (const ulonglong2*)sP;
        u64 v01=0, v23=0, w01=0, w23=0;
        #pragma unroll 4
        for (int k = 0; k < HH; k++) {
            ulonglong2 x = sP2[k];
            u64 wv = pack2(Wv[k*HH + h]);
            u64 ww = pack2(Ww[k*HH + h]);
            v01 = fma2(x.x, wv, v01); v23 = fma2(x.y, wv, v23);
            w01 = fma2(x.x, ww, w01); w23 = fma2(x.y, ww, w23);
        }
        float a,b,c,d, e,f,g,q;
        unpack2(v01, a, b); unpack2(v23, c, d);
        unpack2(w01, e, f); unpack2(w23, g, q);
        g_hv[(size_t)(base+0)*HH + h] = a;
        g_hv[(size_t)(base+1)*HH + h] = b;
        g_hv[(size_t)(base+2)*HH + h] = c;
        g_hv[(size_t)(base+3)*HH + h] = d;
        g_hw[(size_t)(base+0)*HH + h] = e;
        g_hw[(size_t)(base+1)*HH + h] = f;
        g_hw[(size_t)(base+2)*HH + h] = g;
        g_hw[(size_t)(base+3)*HH + h] = q;
    }
}

// ---------------------------------------------------------------------------
// msg: messages[b,v,h] = sum_w [adj!=0] * relu(hv[v,h] + hw[w,h] + e.We)
// Block = 4 v-rows, 256 threads = (vloc = tid&3, q = tid>>2), h-pair = 2q,
// q < 50. All inner operands in smem; per-vloc strides PADDED so the four
// vloc slices occupy disjoint bank groups (R9's 4-way conflict fix).
//   s_hw2 : hw {h,h+1} pairs, whole batch       6400 u64 (51200 B)
//   s_e2  : dup'd {e,e} packs, 4 rows, stride 514   2056 u64
//   s_m2  : dup'd {m,m} masks, stride 130            520 u64
// total 8976 u64 = 71808 B -> 3 blocks/SM. grid = 1024.
// ---------------------------------------------------------------------------
__global__ void __launch_bounds__(256)
k_msg(const float* __restrict__ edges, const float* __restrict__ We) {
    extern __shared__ u64 sm[];
    u64* s_hw2 = sm;                        // [w*50 + p]
    u64* s_e2  = sm + 6400;                 // [v*EV_STRIDE + w*4 + j]
    u64* s_m2  = sm + 6400 + 4*EV_STRIDE;   // [v*MV_STRIDE + w]

    int bx  = blockIdx.x;
    int b   = bx >> 5;
    int v0  = (bx & 31) * 4;
    int tid = threadIdx.x;
    int bN  = b * NN;

    // stage hw pairs for the whole batch (128 rows x 50 pairs)
    for (int i = tid; i < 6400; i += 256) {
        int w = i / 50, p = i - w*50;
        s_hw2[i] = *(const u64*)(g_hw + (size_t)(bN + w)*HH + 2*p);
    }
    // stage edges (dup'd) + masks (dup'd) for 4 v-rows, padded strides
    for (int i = tid; i < 512; i += 256) {
        int v = i >> 7, w = i & 127;
        float4 e = ((const float4*)edges)[(size_t)(bN + v0 + v)*NN + w];
        u64* dst = s_e2 + v*EV_STRIDE + w*4;
        dst[0] = pack2(e.x); dst[1] = pack2(e.y);
        dst[2] = pack2(e.z); dst[3] = pack2(e.w);
        float s = (e.x + e.y) + (e.z + e.w);
        s_m2[v*MV_STRIDE + w] = pack2((s != 0.0f) ? 1.0f : 0.0f);
    }
    __syncthreads();

    int vloc = tid & 3;
    int q    = tid >> 2;
    if (q < 50) {
        int h0  = 2*q;
        int row = bN + v0 + vloc;
        u64 hv2 = *(const u64*)(g_hv + (size_t)row*HH + h0);
        u64 we0 = *(const u64*)(We + 0*HH + h0);
        u64 we1 = *(const u64*)(We + 1*HH + h0);
        u64 we2 = *(const u64*)(We + 2*HH + h0);
        u64 we3 = *(const u64*)(We + 3*HH + h0);

        const u64* ev  = s_e2 + vloc*EV_STRIDE;
        const u64* mv  = s_m2 + vloc*MV_STRIDE;
        const u64* hwp = s_hw2 + q;

        u64 acc0 = 0, acc1 = 0;
        #pragma unroll 4
        for (int w = 0; w < NN; w += 2) {
            // w
            ulonglong2 eA0 = *(const ulonglong2*)(ev + w*4);
            ulonglong2 eB0 = *(const ulonglong2*)(ev + w*4 + 2);
            u64 p0 = add2(hv2, hwp[w*50]);
            p0 = fma2(eA0.x, we0, p0);
            p0 = fma2(eA0.y, we1, p0);
            p0 = fma2(eB0.x, we2, p0);
            p0 = fma2(eB0.y, we3, p0);
            acc0 = fma2(relu2(p0), mv[w], acc0);
            // w+1 (independent chain)
            ulonglong2 eA1 = *(const ulonglong2*)(ev + (w+1)*4);
            ulonglong2 eB1 = *(const ulonglong2*)(ev + (w+1)*4 + 2);
            u64 p1 = add2(hv2, hwp[(w+1)*50]);
            p1 = fma2(eA1.x, we0, p1);
            p1 = fma2(eA1.y, we1, p1);
            p1 = fma2(eB1.x, we2, p1);
            p1 = fma2(eB1.y, we3, p1);
            acc1 = fma2(relu2(p1), mv[w+1], acc1);
        }
        u64 acc = add2(acc0, acc1);
        float a0, a1; unpack2(acc, a0, a1);
        *(float2*)(g_msg + (size_t)row*HH + h0) = make_float2(a0, a1);
    }
}

// ---------------------------------------------------------------------------
// update (masked tanh) fused with proj of the NEW hidden. 4 rows, 128 thr,
// grid 1024.
// ---------------------------------------------------------------------------
__global__ void __launch_bounds__(128)
k_updproj(const float* __restrict__ Wu, const float* __restrict__ Wv,
          const float* __restrict__ Ww) {
    __shared__ float4 sU[2*HH];      // [hidden; msg] transposed
    __shared__ float4 sP[HH];        // new hidden transposed
    int base = blockIdx.x * 4;
    int tid  = threadIdx.x;
    float* sUf = (float*)sU;

    for (int i = tid; i < 4*2*HH; i += 128) {
        int r = i / (2*HH), k = i - r*(2*HH);
        float x = (k < HH) ? g_hidden[(size_t)(base + r)*HH + k]
                           : g_msg   [(size_t)(base + r)*HH + (k - HH)];
        sUf[k*4 + r] = x;
    }
    __syncthreads();

    if (tid < HH) {
        int h = tid;
        const ulonglong2* sU2 = (const ulonglong2*)sU;
        u64 a01=0, a23=0;
        #pragma unroll 4
        for (int k = 0; k < 2*HH; k++) {
            ulonglong2 x = sU2[k];
            u64 w = pack2(Wu[k*HH + h]);
            a01 = fma2(x.x, w, a01);
            a23 = fma2(x.y, w, a23);
        }
        float f0,f1,f2,f3;
        unpack2(a01, f0, f1); unpack2(a23, f2, f3);
        float n0 = g_nodemask[base+0] ? tanhf(f0) : sUf[h*4+0];
        float n1 = g_nodemask[base+1] ? tanhf(f1) : sUf[h*4+1];
        float n2 = g_nodemask[base+2] ? tanhf(f2) : sUf[h*4+2];
        float n3 = g_nodemask[base+3] ? tanhf(f3) : sUf[h*4+3];
        g_hidden[(size_t)(base+0)*HH + h] = n0;
        g_hidden[(size_t)(base+1)*HH + h] = n1;
        g_hidden[(size_t)(base+2)*HH + h] = n2;
        g_hidden[(size_t)(base+3)*HH + h] = n3;
        sP[h] = make_float4(n0, n1, n2, n3);
    }
    __syncthreads();

    if (tid < HH) {
        int h = tid;
        const ulonglong2* sP2 = (const ulonglong2*)sP;
        u64 v01=0, v23=0, w01=0, w23=0;
        #pragma unroll 4
        for (int k = 0; k < HH; k++) {
            ulonglong2 x = sP2[k];
            u64 wv = pack2(Wv[k*HH + h]);
            u64 ww = pack2(Ww[k*HH + h]);
            v01 = fma2(x.x, wv, v01); v23 = fma2(x.y, wv, v23);
            w01 = fma2(x.x, ww, w01); w23 = fma2(x.y, ww, w23);
        }
        float a,b,c,d, e,f,g,q;
        unpack2(v01, a, b); unpack2(v23, c, d);
        unpack2(w01, e, f); unpack2(w23, g, q);
        g_hv[(size_t)(base+0)*HH + h] = a;
        g_hv[(size_t)(base+1)*HH + h] = b;
        g_hv[(size_t)(base+2)*HH + h] = c;
        g_hv[(size_t)(base+3)*HH + h] = d;
        g_hw[(size_t)(base+0)*HH + h] = e;
        g_hw[(size_t)(base+1)*HH + h] = f;
        g_hw[(size_t)(base+2)*HH + h] = g;
        g_hw[(size_t)(base+3)*HH + h] = q;
    }
}

// ---------------------------------------------------------------------------
// final update fused with readout gterm. No g_hidden write needed.
// ---------------------------------------------------------------------------
__global__ void __launch_bounds__(128)
k_updread(const float* __restrict__ nodes, const float* __restrict__ Wu,
          const float* __restrict__ Wr) {
    __shared__ float4 sU[2*HH];      // [hidden; msg]
    __shared__ float4 sR[2*HH];      // [new_hidden; nodes]
    int base = blockIdx.x * 4;
    int tid  = threadIdx.x;
    float* sUf = (float*)sU;
    float* sRf = (float*)sR;

    for (int i = tid; i < 4*2*HH; i += 128) {
        int r = i / (2*HH), k = i - r*(2*HH);
        float x = (k < HH) ? g_hidden[(size_t)(base + r)*HH + k]
                           : g_msg   [(size_t)(base + r)*HH + (k - HH)];
        sUf[k*4 + r] = x;
    }
    for (int i = tid; i < 4*HH; i += 128) {
        int r = i / HH, k = i - r*HH;
        sRf[(HH + k)*4 + r] = nodes[(size_t)(base + r)*HH + k];
    }
    __syncthreads();

    if (tid < HH) {
        int h = tid;
        const ulonglong2* sU2 = (const ulonglong2*)sU;
        u64 a01=0, a23=0;
        #pragma unroll 4
        for (int k = 0; k < 2*HH; k++) {
            ulonglong2 x = sU2[k];
            u64 w = pack2(Wu[k*HH + h]);
            a01 = fma2(x.x, w, a01);
            a23 = fma2(x.y, w, a23);
        }
        float f0,f1,f2,f3;
        unpack2(a01, f0, f1); unpack2(a23, f2, f3);
        float n0 = g_nodemask[base+0] ? tanhf(f0) : sUf[h*4+0];
        float n1 = g_nodemask[base+1] ? tanhf(f1) : sUf[h*4+1];
        float n2 = g_nodemask[base+2] ? tanhf(f2) : sUf[h*4+2];
        float n3 = g_nodemask[base+3] ? tanhf(f3) : sUf[h*4+3];
        sR[h] = make_float4(n0, n1, n2, n3);
    }
    __syncthreads();

    if (tid < HH) {
        int h = tid;
        const ulonglong2* sR2 = (const ulonglong2*)sR;
        u64 a01=0, a23=0;
        #pragma unroll 4
        for (int k = 0; k < 2*HH; k++) {
            ulonglong2 x = sR2[k];
            u64 w = pack2(Wr[k*HH + h]);
            a01 = fma2(x.x, w, a01);
            a23 = fma2(x.y, w, a23);
        }
        float f0,f1,f2,f3;
        unpack2(a01, f0, f1); unpack2(a23, f2, f3);
        float m0 = g_nodemask[base+0] ? 1.f : 0.f;
        float m1 = g_nodemask[base+1] ? 1.f : 0.f;
        float m2 = g_nodemask[base+2] ? 1.f : 0.f;
        float m3 = g_nodemask[base+3] ? 1.f : 0.f;
        g_gterm[(size_t)(base+0)*HH + h] = fmaxf(f0, 0.f) * m0;
        g_gterm[(size_t)(base+1)*HH + h] = fmaxf(f1, 0.f) * m1;
        g_gterm[(size_t)(base+2)*HH + h] = fmaxf(f2, 0.f) * m2;
        g_gterm[(size_t)(base+3)*HH + h] = fmaxf(f3, 0.f) * m3;
    }
}

// ---------------------------------------------------------------------------
// reduce: out[b,h] = sum_v gterm[b,v,h]  (deterministic, no atomics)
// ---------------------------------------------------------------------------
__global__ void k_reduce(float* __restrict__ out) {
    int b   = blockIdx.x;
    int tid = threadIdx.x;           // 512
    int q   = tid >> 7;
    int h   = tid & 127;
    __shared__ float red[4][128];
    float acc = 0.f;
    if (h < HH) {
        int v0 = q * 32;
        #pragma unroll 4
        for (int v = v0; v < v0 + 32; v++)
            acc += g_gterm[(size_t)(b*NN + v)*HH + h];
    }
    red[q][h] = acc;
    __syncthreads();
    if (q == 0 && h < HH)
        out[b*HH + h] = (red[0][h] + red[1][h]) + (red[2][h] + red[3][h]);
}

extern "C" void kernel_launch(void* const* d_in, const int* in_sizes, int n_in,
                              void* d_out, int out_size) {
    const float* nodes = (const float*)d_in[0];
    const float* edges = (const float*)d_in[1];
    const float* Wv    = (const float*)d_in[2];
    const float* Ww    = (const float*)d_in[3];
    const float* We    = (const float*)d_in[4];
    const float* Wu    = (const float*)d_in[5];
    const float* Wr    = (const float*)d_in[6];
    float* out = (float*)d_out;

    const int msg_smem = (6400 + 4*EV_STRIDE + 4*MV_STRIDE) * 8;  // 71808
    cudaFuncSetAttribute(k_msg, cudaFuncAttributeMaxDynamicSharedMemorySize, msg_smem);

    k_init_proj<<<ROWS/4, 128>>>(nodes, edges, Wv, Ww);
    for (int p = 0; p < 2; p++) {
        k_msg<<<1024, 256, msg_smem>>>(edges, We);
        k_updproj<<<ROWS/4, 128>>>(Wu, Wv, Ww);
    }
    k_msg<<<1024, 256, msg_smem>>>(edges, We);
    k_updread<<<ROWS/4, 128>>>(nodes, Wu, Wr);
    k_reduce<<<BB, 512>>>(out);
}

// round 11
// speedup vs baseline: 2.7330x; 1.4438x over previous
#include <cuda_runtime.h>

#define BB 32
#define NN 128
#define HH 100
#define ROWS (BB*NN)    // 4096

// k_msg w-split tile geometry (padded strides keep vloc slices 4 banks apart)
#define WH 64           // w-half size
#define EV_STRIDE 258   // u64 per vloc slice of edges (64*4 + 2 pad)
#define MV_STRIDE 66    // u64 per vloc slice of masks (64 + 2 pad)
#define MSG_SMEM_U64 (3200 + 8*EV_STRIDE + 8*MV_STRIDE)   // 5792 u64 = 46336 B

// Scratch (static device allocations — allowed)
__device__ float g_hidden[ROWS*HH];
__device__ float g_hv[ROWS*HH];
__device__ float g_hw[ROWS*HH];
__device__ float g_msg [ROWS*HH];   // w in [0,64)
__device__ float g_msg2[ROWS*HH];   // w in [64,128)
__device__ float g_gterm[ROWS*HH];
__device__ int   g_nodemask[ROWS];

typedef unsigned long long u64;

__device__ __forceinline__ u64 fma2(u64 a, u64 b, u64 c) {
    u64 d;
    asm("fma.rn.f32x2 %0, %1, %2, %3;" : "=l"(d) : "l"(a), "l"(b), "l"(c));
    return d;
}
__device__ __forceinline__ u64 add2(u64 a, u64 b) {
    u64 d;
    asm("add.rn.f32x2 %0, %1, %2;" : "=l"(d) : "l"(a), "l"(b));
    return d;
}
__device__ __forceinline__ u64 pack2(float w) {
    u64 d;
    asm("mov.b64 %0, {%1, %1};" : "=l"(d) : "f"(w));
    return d;
}
__device__ __forceinline__ u64 packlh(float lo, float hi) {
    u64 d;
    asm("mov.b64 %0, {%1, %2};" : "=l"(d) : "f"(lo), "f"(hi));
    return d;
}
__device__ __forceinline__ void unpack2(u64 v, float& lo, float& hi) {
    asm("mov.b64 {%0, %1}, %2;" : "=f"(lo), "=f"(hi) : "l"(v));
}
__device__ __forceinline__ u64 relu2(u64 v) {
    float lo, hi;
    unpack2(v, lo, hi);
    return packlh(fmaxf(lo, 0.f), fmaxf(hi, 0.f));
}

// ---------------------------------------------------------------------------
// init + mask + proj of pass 1. Block = 4 rows, 128 threads, grid 1024.
// ---------------------------------------------------------------------------
__global__ void __launch_bounds__(128)
k_init_proj(const float* __restrict__ nodes, const float* __restrict__ edges,
            const float* __restrict__ Wv, const float* __restrict__ Ww) {
    __shared__ float4 sP[HH];        // nodes transposed: sP[k] = rows 0..3
    int base = blockIdx.x * 4;
    int tid  = threadIdx.x;

    {
        int r = tid >> 5, lane = tid & 31;
        const float4* e4 = (const float4*)edges + (size_t)(base + r) * NN;
        float s = 0.f;
        #pragma unroll
        for (int j = 0; j < 4; j++) {
            float4 e = e4[lane + 32*j];
            s += (e.x + e.y) + (e.z + e.w);
        }
        #pragma unroll
        for (int off = 16; off > 0; off >>= 1)
            s += __shfl_xor_sync(0xffffffffu, s, off);
        if (lane == 0) g_nodemask[base + r] = (s != 0.0f) ? 1 : 0;
    }

    if (tid < HH) {
        int h = tid;
        float x0 = nodes[(size_t)(base+0)*HH + h];
        float x1 = nodes[(size_t)(base+1)*HH + h];
        float x2 = nodes[(size_t)(base+2)*HH + h];
        float x3 = nodes[(size_t)(base+3)*HH + h];
        g_hidden[(size_t)(base+0)*HH + h] = x0;
        g_hidden[(size_t)(base+1)*HH + h] = x1;
        g_hidden[(size_t)(base+2)*HH + h] = x2;
        g_hidden[(size_t)(base+3)*HH + h] = x3;
        sP[h] = make_float4(x0, x1, x2, x3);
    }
    __syncthreads();

    if (tid < HH) {
        int h = tid;
        const ulonglong2* sP2 = (const ulonglong2*)sP;
        u64 v01=0, v23=0, w01=0, w23=0;
        #pragma unroll 4
        for (int k = 0; k < HH; k++) {
            ulonglong2 x = sP2[k];
            u64 wv = pack2(Wv[k*HH + h]);
            u64 ww = pack2(Ww[k*HH + h]);
            v01 = fma2(x.x, wv, v01); v23 = fma2(x.y, wv, v23);
            w01 = fma2(x.x, ww, w01); w23 = fma2(x.y, ww, w23);
        }
        float a,b,c,d, e,f,g,q;
        unpack2(v01, a, b); unpack2(v23, c, d);
        unpack2(w01, e, f); unpack2(w23, g, q);
        g_hv[(size_t)(base+0)*HH + h] = a;
        g_hv[(size_t)(base+1)*HH + h] = b;
        g_hv[(size_t)(base+2)*HH + h] = c;
        g_hv[(size_t)(base+3)*HH + h] = d;
        g_hw[(size_t)(base+0)*HH + h] = e;
        g_hw[(size_t)(base+1)*HH + h] = f;
        g_hw[(size_t)(base+2)*HH + h] = g;
        g_hw[(size_t)(base+3)*HH + h] = q;
    }
}

// ---------------------------------------------------------------------------
// msg (w-split): partial[b,v,h] = sum_{w in half} [adj!=0]*relu(hv+hw+e.We)
// Block = 8 v-rows x one w-half, 512 threads, grid = 1024
// (bx: half = bx&1, vgroup = (bx>>1)&15, b = bx>>5).
// Thread map: t<400 active, vloc = t/50, p = t%50, h-pair = 2p.
// smem (46336 B -> 4 blocks/SM = 64 warps/SM):
//   s_hw2 : hw {h,h+1} pairs for the w-half      3200 u64 (25.6 KB)
//   s_e2  : dup'd {e,e} packs, 8 rows, stride 258
//   s_m2  : dup'd {m,m} masks, stride 66
// ---------------------------------------------------------------------------
__global__ void __launch_bounds__(512)
k_msg(const float* __restrict__ edges, const float* __restrict__ We) {
    extern __shared__ u64 sm[];
    u64* s_hw2 = sm;                        // [wl*50 + p]
    u64* s_e2  = sm + 3200;                 // [v*EV_STRIDE + wl*4 + j]
    u64* s_m2  = sm + 3200 + 8*EV_STRIDE;   // [v*MV_STRIDE + wl]

    int bx   = blockIdx.x;
    int half = bx & 1;
    int v0   = ((bx >> 1) & 15) * 8;
    int b    = bx >> 5;
    int wofs = half * WH;
    int tid  = threadIdx.x;
    int bN   = b * NN;
    float* outp = half ? g_msg2 : g_msg;

    // stage hw pairs for this w-half (64 rows x 50 pairs)
    for (int i = tid; i < WH*50; i += 512) {
        int wl = i / 50, p = i - wl*50;
        s_hw2[i] = *(const u64*)(g_hw + (size_t)(bN + wofs + wl)*HH + 2*p);
    }
    // stage edges (dup'd) + masks (dup'd) for 8 v-rows x 64 w
    for (int i = tid; i < 8*WH; i += 512) {
        int v = i >> 6, wl = i & 63;
        float4 e = ((const float4*)edges)[(size_t)(bN + v0 + v)*NN + wofs + wl];
        u64* dst = s_e2 + v*EV_STRIDE + wl*4;
        dst[0] = pack2(e.x); dst[1] = pack2(e.y);
        dst[2] = pack2(e.z); dst[3] = pack2(e.w);
        float s = (e.x + e.y) + (e.z + e.w);
        s_m2[v*MV_STRIDE + wl] = pack2((s != 0.0f) ? 1.0f : 0.0f);
    }
    __syncthreads();

    if (tid < 400) {
        int vloc = tid / 50;
        int p    = tid - vloc*50;
        int h0   = 2*p;
        int row  = bN + v0 + vloc;
        u64 hv2 = *(const u64*)(g_hv + (size_t)row*HH + h0);
        u64 we0 = *(const u64*)(We + 0*HH + h0);
        u64 we1 = *(const u64*)(We + 1*HH + h0);
        u64 we2 = *(const u64*)(We + 2*HH + h0);
        u64 we3 = *(const u64*)(We + 3*HH + h0);

        const u64* ev  = s_e2 + vloc*EV_STRIDE;
        const u64* mv  = s_m2 + vloc*MV_STRIDE;
        const u64* hwp = s_hw2 + p;

        u64 acc0 = 0, acc1 = 0;
        #pragma unroll 4
        for (int wl = 0; wl < WH; wl += 2) {
            ulonglong2 eA0 = *(const ulonglong2*)(ev + wl*4);
            ulonglong2 eB0 = *(const ulonglong2*)(ev + wl*4 + 2);
            u64 p0 = add2(hv2, hwp[wl*50]);
            p0 = fma2(eA0.x, we0, p0);
            p0 = fma2(eA0.y, we1, p0);
            p0 = fma2(eB0.x, we2, p0);
            p0 = fma2(eB0.y, we3, p0);
            acc0 = fma2(relu2(p0), mv[wl], acc0);

            ulonglong2 eA1 = *(const ulonglong2*)(ev + (wl+1)*4);
            ulonglong2 eB1 = *(const ulonglong2*)(ev + (wl+1)*4 + 2);
            u64 p1 = add2(hv2, hwp[(wl+1)*50]);
            p1 = fma2(eA1.x, we0, p1);
            p1 = fma2(eA1.y, we1, p1);
            p1 = fma2(eB1.x, we2, p1);
            p1 = fma2(eB1.y, we3, p1);
            acc1 = fma2(relu2(p1), mv[wl+1], acc1);
        }
        u64 acc = add2(acc0, acc1);
        float a0, a1; unpack2(acc, a0, a1);
        *(float2*)(outp + (size_t)row*HH + h0) = make_float2(a0, a1);
    }
}

// ---------------------------------------------------------------------------
// update (masked tanh) fused with proj of the NEW hidden. 4 rows, 128 thr,
// grid 1024. msg = g_msg + g_msg2 (the two w-half partials).
// ---------------------------------------------------------------------------
__global__ void __launch_bounds__(128)
k_updproj(const float* __restrict__ Wu, const float* __restrict__ Wv,
          const float* __restrict__ Ww) {
    __shared__ float4 sU[2*HH];      // [hidden; msg] transposed
    __shared__ float4 sP[HH];        // new hidden transposed
    int base = blockIdx.x * 4;
    int tid  = threadIdx.x;
    float* sUf = (float*)sU;

    for (int i = tid; i < 4*2*HH; i += 128) {
        int r = i / (2*HH), k = i - r*(2*HH);
        size_t idx = (size_t)(base + r)*HH;
        float x = (k < HH) ? g_hidden[idx + k]
                           : (g_msg[idx + (k - HH)] + g_msg2[idx + (k - HH)]);
        sUf[k*4 + r] = x;
    }
    __syncthreads();

    if (tid < HH) {
        int h = tid;
        const ulonglong2* sU2 = (const ulonglong2*)sU;
        u64 a01=0, a23=0;
        #pragma unroll 4
        for (int k = 0; k < 2*HH; k++) {
            ulonglong2 x = sU2[k];
            u64 w = pack2(Wu[k*HH + h]);
            a01 = fma2(x.x, w, a01);
            a23 = fma2(x.y, w, a23);
        }
        float f0,f1,f2,f3;
        unpack2(a01, f0, f1); unpack2(a23, f2, f3);
        float n0 = g_nodemask[base+0] ? tanhf(f0) : sUf[h*4+0];
        float n1 = g_nodemask[base+1] ? tanhf(f1) : sUf[h*4+1];
        float n2 = g_nodemask[base+2] ? tanhf(f2) : sUf[h*4+2];
        float n3 = g_nodemask[base+3] ? tanhf(f3) : sUf[h*4+3];
        g_hidden[(size_t)(base+0)*HH + h] = n0;
        g_hidden[(size_t)(base+1)*HH + h] = n1;
        g_hidden[(size_t)(base+2)*HH + h] = n2;
        g_hidden[(size_t)(base+3)*HH + h] = n3;
        sP[h] = make_float4(n0, n1, n2, n3);
    }
    __syncthreads();

    if (tid < HH) {
        int h = tid;
        const ulonglong2* sP2 = (const ulonglong2*)sP;
        u64 v01=0, v23=0, w01=0, w23=0;
        #pragma unroll 4
        for (int k = 0; k < HH; k++) {
            ulonglong2 x = sP2[k];
            u64 wv = pack2(Wv[k*HH + h]);
            u64 ww = pack2(Ww[k*HH + h]);
            v01 = fma2(x.x, wv, v01); v23 = fma2(x.y, wv, v23);
            w01 = fma2(x.x, ww, w01); w23 = fma2(x.y, ww, w23);
        }
        float a,b,c,d, e,f,g,q;
        unpack2(v01, a, b); unpack2(v23, c, d);
        unpack2(w01, e, f); unpack2(w23, g, q);
        g_hv[(size_t)(base+0)*HH + h] = a;
        g_hv[(size_t)(base+1)*HH + h] = b;
        g_hv[(size_t)(base+2)*HH + h] = c;
        g_hv[(size_t)(base+3)*HH + h] = d;
        g_hw[(size_t)(base+0)*HH + h] = e;
        g_hw[(size_t)(base+1)*HH + h] = f;
        g_hw[(size_t)(base+2)*HH + h] = g;
        g_hw[(size_t)(base+3)*HH + h] = q;
    }
}

// ---------------------------------------------------------------------------
// final update fused with readout gterm. No g_hidden write needed.
// ---------------------------------------------------------------------------
__global__ void __launch_bounds__(128)
k_updread(const float* __restrict__ nodes, const float* __restrict__ Wu,
          const float* __restrict__ Wr) {
    __shared__ float4 sU[2*HH];      // [hidden; msg]
    __shared__ float4 sR[2*HH];      // [new_hidden; nodes]
    int base = blockIdx.x * 4;
    int tid  = threadIdx.x;
    float* sUf = (float*)sU;
    float* sRf = (float*)sR;

    for (int i = tid; i < 4*2*HH; i += 128) {
        int r = i / (2*HH), k = i - r*(2*HH);
        size_t idx = (size_t)(base + r)*HH;
        float x = (k < HH) ? g_hidden[idx + k]
                           : (g_msg[idx + (k - HH)] + g_msg2[idx + (k - HH)]);
        sUf[k*4 + r] = x;
    }
    for (int i = tid; i < 4*HH; i += 128) {
        int r = i / HH, k = i - r*HH;
        sRf[(HH + k)*4 + r] = nodes[(size_t)(base + r)*HH + k];
    }
    __syncthreads();

    if (tid < HH) {
        int h = tid;
        const ulonglong2* sU2 = (const ulonglong2*)sU;
        u64 a01=0, a23=0;
        #pragma unroll 4
        for (int k = 0; k < 2*HH; k++) {
            ulonglong2 x = sU2[k];
            u64 w = pack2(Wu[k*HH + h]);
            a01 = fma2(x.x, w, a01);
            a23 = fma2(x.y, w, a23);
        }
        float f0,f1,f2,f3;
        unpack2(a01, f0, f1); unpack2(a23, f2, f3);
        float n0 = g_nodemask[base+0] ? tanhf(f0) : sUf[h*4+0];
        float n1 = g_nodemask[base+1] ? tanhf(f1) : sUf[h*4+1];
        float n2 = g_nodemask[base+2] ? tanhf(f2) : sUf[h*4+2];
        float n3 = g_nodemask[base+3] ? tanhf(f3) : sUf[h*4+3];
        sR[h] = make_float4(n0, n1, n2, n3);
    }
    __syncthreads();

    if (tid < HH) {
        int h = tid;
        const ulonglong2* sR2 = (const ulonglong2*)sR;
        u64 a01=0, a23=0;
        #pragma unroll 4
        for (int k = 0; k < 2*HH; k++) {
            ulonglong2 x = sR2[k];
            u64 w = pack2(Wr[k*HH + h]);
            a01 = fma2(x.x, w, a01);
            a23 = fma2(x.y, w, a23);
        }
        float f0,f1,f2,f3;
        unpack2(a01, f0, f1); unpack2(a23, f2, f3);
        float m0 = g_nodemask[base+0] ? 1.f : 0.f;
        float m1 = g_nodemask[base+1] ? 1.f : 0.f;
        float m2 = g_nodemask[base+2] ? 1.f : 0.f;
        float m3 = g_nodemask[base+3] ? 1.f : 0.f;
        g_gterm[(size_t)(base+0)*HH + h] = fmaxf(f0, 0.f) * m0;
        g_gterm[(size_t)(base+1)*HH + h] = fmaxf(f1, 0.f) * m1;
        g_gterm[(size_t)(base+2)*HH + h] = fmaxf(f2, 0.f) * m2;
        g_gterm[(size_t)(base+3)*HH + h] = fmaxf(f3, 0.f) * m3;
    }
}

// ---------------------------------------------------------------------------
// reduce: out[b,h] = sum_v gterm[b,v,h]  (deterministic, no atomics)
// ---------------------------------------------------------------------------
__global__ void k_reduce(float* __restrict__ out) {
    int b   = blockIdx.x;
    int tid = threadIdx.x;           // 512
    int q   = tid >> 7;
    int h   = tid & 127;
    __shared__ float red[4][128];
    float acc = 0.f;
    if (h < HH) {
        int v0 = q * 32;
        #pragma unroll 4
        for (int v = v0; v < v0 + 32; v++)
            acc += g_gterm[(size_t)(b*NN + v)*HH + h];
    }
    red[q][h] = acc;
    __syncthreads();
    if (q == 0 && h < HH)
        out[b*HH + h] = (red[0][h] + red[1][h]) + (red[2][h] + red[3][h]);
}

extern "C" void kernel_launch(void* const* d_in, const int* in_sizes, int n_in,
                              void* d_out, int out_size) {
    const float* nodes = (const float*)d_in[0];
    const float* edges = (const float*)d_in[1];
    const float* Wv    = (const float*)d_in[2];
    const float* Ww    = (const float*)d_in[3];
    const float* We    = (const float*)d_in[4];
    const float* Wu    = (const float*)d_in[5];
    const float* Wr    = (const float*)d_in[6];
    float* out = (float*)d_out;

    const int msg_smem = MSG_SMEM_U64 * 8;   // 46336 B
    cudaFuncSetAttribute(k_msg, cudaFuncAttributeMaxDynamicSharedMemorySize, msg_smem);

    k_init_proj<<<ROWS/4, 128>>>(nodes, edges, Wv, Ww);
    for (int p = 0; p < 2; p++) {
        k_msg<<<1024, 512, msg_smem>>>(edges, We);
        k_updproj<<<ROWS/4, 128>>>(Wu, Wv, Ww);
    }
    k_msg<<<1024, 512, msg_smem>>>(edges, We);
    k_updread<<<ROWS/4, 128>>>(nodes, Wu, Wr);
    k_reduce<<<BB, 512>>>(out);
}